// round 12
// baseline (speedup 1.0000x reference)
#include <cuda_runtime.h>
#include <cuda_bf16.h>
#include <cstdint>
#include <math.h>

#define BSZ   2048
#define NROWS (BSZ * 63)   // 129024

// ---- scratch (pre-split bf16 hi/lo activations) ----
__device__ __nv_bfloat16 g_X1h[(size_t)NROWS * 256], g_X1l[(size_t)NROWS * 256];
__device__ __nv_bfloat16 g_reph[(size_t)NROWS * 128], g_repl[(size_t)NROWS * 128];

// split-bf16 weights, transposed to [N][K]
__device__ __nv_bfloat16 g_W1h[256 * 512],  g_W1l[256 * 512];
__device__ __nv_bfloat16 g_W2h[128 * 256],  g_W2l[128 * 256];
__device__ __nv_bfloat16 g_Wbmh[64 * 1024], g_Wbml[64 * 1024];
__device__ __nv_bfloat16 g_Woph[64 * 64],   g_Wopl[64 * 64];
__device__ __nv_bfloat16 g_Wprh[64 * 64],   g_Wprl[64 * 64];

// ---- helpers ----
#define SWZ(o) ((o) ^ (((o) >> 3) & 0x70))

__device__ __forceinline__ uint32_t smem_u32(const void* p) {
    uint32_t a;
    asm("{ .reg .u64 t; cvta.to.shared.u64 t, %1; cvt.u32.u64 %0, t; }" : "=r"(a) : "l"(p));
    return a;
}
__device__ __forceinline__ void ldsm4(uint32_t* r, uint32_t addr) {
    asm volatile("ldmatrix.sync.aligned.m8n8.x4.shared.b16 {%0,%1,%2,%3}, [%4];"
                 : "=r"(r[0]), "=r"(r[1]), "=r"(r[2]), "=r"(r[3]) : "r"(addr));
}
__device__ __forceinline__ void mma16816(float* c, const uint32_t* a, const uint32_t* b) {
    asm volatile("mma.sync.aligned.m16n8k16.row.col.f32.bf16.bf16.f32 "
                 "{%0,%1,%2,%3}, {%4,%5,%6,%7}, {%8,%9}, {%0,%1,%2,%3};"
                 : "+f"(c[0]), "+f"(c[1]), "+f"(c[2]), "+f"(c[3])
                 : "r"(a[0]), "r"(a[1]), "r"(a[2]), "r"(a[3]), "r"(b[0]), "r"(b[1]));
}
__device__ __forceinline__ void cpa16(uint32_t dst, const void* src) {
    asm volatile("cp.async.cg.shared.global [%0], [%1], 16;" :: "r"(dst), "l"(src) : "memory");
}
__device__ __forceinline__ void cpcommit() { asm volatile("cp.async.commit_group;" ::: "memory"); }
__device__ __forceinline__ void cpwait0()  { asm volatile("cp.async.wait_group 0;" ::: "memory"); }
__device__ __forceinline__ void cpwait1()  { asm volatile("cp.async.wait_group 1;" ::: "memory"); }

__device__ __forceinline__ void split2(float x, float y, uint32_t& hi, uint32_t& lo) {
    float2 f = make_float2(x, y);
    __nv_bfloat162 h = __float22bfloat162_rn(f);
    float2 r = make_float2(x - __bfloat162float(h.x), y - __bfloat162float(h.y));
    __nv_bfloat162 l = __float22bfloat162_rn(r);
    hi = *reinterpret_cast<uint32_t*>(&h);
    lo = *reinterpret_cast<uint32_t*>(&l);
}
__device__ __forceinline__ void splitw(float v, __nv_bfloat16* ph, __nv_bfloat16* pl) {
    __nv_bfloat16 h = __float2bfloat16(v);
    *ph = h;
    *pl = __float2bfloat16(v - __bfloat162float(h));
}

// ---- weight prep ----
__global__ void __launch_bounds__(256) prep_kernel(
    const float* __restrict__ W1, const float* __restrict__ W2,
    const float* __restrict__ Wbm, const float* __restrict__ Wop,
    const float* __restrict__ Wpr)
{
    int idx = blockIdx.x * 256 + threadIdx.x;
    if (idx < 131072) { int n = idx >> 9, k = idx & 511;
        splitw(W1[k * 256 + n], &g_W1h[idx], &g_W1l[idx]); return; }
    idx -= 131072;
    if (idx < 32768) { int n = idx >> 8, k = idx & 255;
        splitw(W2[k * 128 + n], &g_W2h[idx], &g_W2l[idx]); return; }
    idx -= 32768;
    if (idx < 65536) { int n = idx >> 10, k = idx & 1023;
        float v = (k < 1000) ? Wbm[k * 64 + n] : 0.f;
        splitw(v, &g_Wbmh[idx], &g_Wbml[idx]); return; }
    idx -= 65536;
    if (idx < 4096) { int n = idx >> 6, k = idx & 63;
        splitw(Wop[k * 64 + n], &g_Woph[idx], &g_Wopl[idx]); return; }
    idx -= 4096;
    if (idx < 4096) { int n = idx >> 6, k = idx & 63;
        splitw(Wpr[k * 64 + n], &g_Wprh[idx], &g_Wprl[idx]); }
}

// ============================================================
// Input kernel v4 (round-10 proven): M=64 rows/CTA, 256 threads, 3 CTAs/SM.
// A prefetched into registers one chunk ahead; B via cp.async 2-ring.
// SMEM: A 2x16K @0 | B 2x16K @32768
// ============================================================
__global__ void __launch_bounds__(256, 3) input_kernel(
    const float* __restrict__ op, const float* __restrict__ extra,
    const float* __restrict__ c1, const float* __restrict__ c2,
    const float* __restrict__ bm, const float* __restrict__ hc,
    const float* __restrict__ bop, const float* __restrict__ bpr,
    const float* __restrict__ bbm)
{
    extern __shared__ char smem[];
    const uint32_t sb = smem_u32(smem);
    const int tid = threadIdx.x, m0 = blockIdx.x * 64;
    const int wid = tid >> 5, lane = tid & 31;
    const int wm = wid & 3, wn = wid >> 2;   // 4m x 2n

    float4 pre[4];
    auto loadA_regs = [&](int s) {
        #pragma unroll
        for (int i = 0; i < 4; i++) {
            int idx = i * 256 + tid;
            int row = idx >> 4, q4 = idx & 15;
            float4 v = make_float4(0.f, 0.f, 0.f, 0.f);
            if (s == 0) {
                int kl = q4 * 4;
                v = (kl < 32) ? *(const float4*)(op    + (size_t)(m0 + row) * 32 + kl)
                              : *(const float4*)(extra + (size_t)(m0 + row) * 32 + kl - 32);
            } else if (s == 1) {
                v = *(const float4*)(c1 + (size_t)(m0 + row) * 64 + q4 * 4);
            } else if (s == 2) {
                v = *(const float4*)(c2 + (size_t)(m0 + row) * 64 + q4 * 4);
            } else {
                int kg4 = (s - 3) * 16 + q4;
                if (kg4 < 250) v = *(const float4*)(bm + (size_t)(m0 + row) * 1000 + kg4 * 4);
            }
            pre[i] = v;
        }
    };
    auto loadB = [&](int s) {
        const int st = s & 1;
        const __nv_bfloat16 *Wh, *Wl;
        int stride, koff;
        if (s == 0)      { Wh = g_Woph; Wl = g_Wopl; stride = 64;   koff = 0; }
        else if (s <= 2) { Wh = g_Wprh; Wl = g_Wprl; stride = 64;   koff = 0; }
        else             { Wh = g_Wbmh; Wl = g_Wbml; stride = 1024; koff = (s - 3) * 64; }
        #pragma unroll
        for (int i = 0; i < 4; i++) {
            int idx = i * 256 + tid;
            int half = idx >> 9, j = idx & 511, n = j >> 3, q = j & 7;
            cpa16(sb + 32768 + st * 16384 + half * 8192 + SWZ((uint32_t)(n * 128 + q * 16)),
                  (half ? Wl : Wh) + (size_t)n * stride + koff + q * 8);
        }
    };

    float C[2][2][4] = {};
    loadA_regs(0);
    loadB(0); cpcommit();

    for (int s = 0; s < 19; s++) {
        const int st = s & 1;
        __syncthreads();
        #pragma unroll
        for (int i = 0; i < 4; i++) {
            int idx = i * 256 + tid;
            int row = idx >> 4, q4 = idx & 15;
            uint32_t h0, l0, h1, l1;
            split2(pre[i].x, pre[i].y, h0, l0);
            split2(pre[i].z, pre[i].w, h1, l1);
            uint32_t o = SWZ((uint32_t)(row * 128 + q4 * 8));
            *(uint2*)(smem + st * 16384 + o)        = make_uint2(h0, h1);
            *(uint2*)(smem + st * 16384 + 8192 + o) = make_uint2(l0, l1);
        }
        if (s + 1 < 19) { loadA_regs(s + 1); loadB(s + 1); }
        cpcommit();
        cpwait1();
        __syncthreads();

        const uint32_t aH = sb + st * 16384, aL = aH + 8192;
        const uint32_t bH = sb + 32768 + st * 16384, bL = bH + 8192;
        #pragma unroll
        for (int k16 = 0; k16 < 4; k16++) {
            const int k0 = k16 * 16;
            uint32_t ah[4], al[4];
            const uint32_t o = SWZ((uint32_t)((wm * 16 + (lane & 15)) * 128 + k0 * 2 + (lane >> 4) * 16));
            ldsm4(ah, aH + o);
            ldsm4(al, aL + o);
            uint32_t bh[2][4], bl[2][4];
            #pragma unroll
            for (int j = 0; j < 2; j++) {
                const int brow = wn * 32 + j * 16 + ((lane >> 4) << 3) + (lane & 7);
                const uint32_t bo = SWZ((uint32_t)(brow * 128 + (k0 + ((lane >> 3) & 1) * 8) * 2));
                ldsm4(bh[j], bH + bo);
                ldsm4(bl[j], bL + bo);
            }
            #pragma unroll
            for (int j = 0; j < 2; j++) { mma16816(C[j][0], ah, bh[j]); mma16816(C[j][1], ah, bh[j] + 2); }
            #pragma unroll
            for (int j = 0; j < 2; j++) { mma16816(C[j][0], al, bh[j]); mma16816(C[j][1], al, bh[j] + 2); }
            #pragma unroll
            for (int j = 0; j < 2; j++) { mma16816(C[j][0], ah, bl[j]); mma16816(C[j][1], ah, bl[j] + 2); }
        }

        if (s <= 2 || s == 18) {
            const int colbase = (s <= 2) ? s * 64 : 192;
            const float* bias = (s == 0) ? bop : (s <= 2 ? bpr : bbm);
            const bool isbm = (s == 18);
            const int r1 = m0 + wm * 16 + (lane >> 2);
            const int r2 = r1 + 8;
            float hv1 = 1.f, hv2 = 1.f;
            if (isbm) { hv1 = hc[r1]; hv2 = hc[r2]; }
            #pragma unroll
            for (int j = 0; j < 2; j++)
                #pragma unroll
                for (int h8 = 0; h8 < 2; h8++) {
                    const int n = wn * 32 + j * 16 + h8 * 8 + (lane & 3) * 2;
                    float2 bb = *(const float2*)(bias + n);
                    float v0 = (C[j][h8][0] + bb.x) * hv1, v1 = (C[j][h8][1] + bb.y) * hv1;
                    float v2 = (C[j][h8][2] + bb.x) * hv2, v3 = (C[j][h8][3] + bb.y) * hv2;
                    uint32_t h01, l01, h23, l23;
                    split2(v0, v1, h01, l01); split2(v2, v3, h23, l23);
                    size_t o1 = (size_t)r1 * 256 + colbase + n;
                    size_t o2 = (size_t)r2 * 256 + colbase + n;
                    *(uint32_t*)(g_X1h + o1) = h01; *(uint32_t*)(g_X1l + o1) = l01;
                    *(uint32_t*)(g_X1h + o2) = h23; *(uint32_t*)(g_X1l + o2) = l23;
                    #pragma unroll
                    for (int q = 0; q < 4; q++) C[j][h8][q] = 0.f;
                }
        }
    }
}

// ============================================================
// Tree level body, MT=64, 512 threads (4m x 4n), act-guarded. (r10 verbatim)
// SMEM: A 2x16K @0 | B1 2x64K @65536 | H @65536(+65536 lo) | B2 @0 2x32K
// ============================================================
__device__ __forceinline__ void tree_body64(
    char* smem, uint32_t sb, int tid, int lane, int wm, int wn,
    const float* b1, const float* b2, int lvl, int m0, int act)
{
    const int nl = 1 << lvl;
    const int lmax = (BSZ << lvl) - 1;

    auto loadA1 = [&](int c, int buf) {
        const uint32_t base = sb + buf * 16384;
        int row = tid >> 3, q = tid & 7;
        int lm = m0 + row; if (lm > lmax) lm = lmax;
        int lb = lm >> lvl, lj = (nl - 1) + (lm & (nl - 1));
        const __nv_bfloat16* src;
        if (c < 4)      src = g_X1h + (size_t)(lb * 63 + lj) * 256 + c * 64 + q * 8;
        else if (c < 6) src = g_reph + (size_t)(lb * 63 + 2 * lj + 1) * 128 + (c - 4) * 64 + q * 8;
        else            src = g_reph + (size_t)(lb * 63 + 2 * lj + 2) * 128 + (c - 6) * 64 + q * 8;
        cpa16(base + SWZ((uint32_t)(row * 128 + q * 16)), src);
        if (c < 4)      src = g_X1l + (size_t)(lb * 63 + lj) * 256 + c * 64 + q * 8;
        else if (c < 6) src = g_repl + (size_t)(lb * 63 + 2 * lj + 1) * 128 + (c - 4) * 64 + q * 8;
        else            src = g_repl + (size_t)(lb * 63 + 2 * lj + 2) * 128 + (c - 6) * 64 + q * 8;
        cpa16(base + 8192 + SWZ((uint32_t)(row * 128 + q * 16)), src);
    };
    auto loadB1 = [&](int c, int buf) {
        const uint32_t base = sb + 65536 + buf * 65536;
        #pragma unroll
        for (int i = 0; i < 8; i++) {
            int idx = i * 512 + tid;
            int half = idx >> 11, j = idx & 2047, n = j >> 3, q = j & 7;
            cpa16(base + half * 32768 + SWZ((uint32_t)(n * 128 + q * 16)),
                  (half ? g_W1l : g_W1h) + (size_t)n * 512 + c * 64 + q * 8);
        }
    };
    auto loadB2 = [&](int c, int buf) {
        const uint32_t base = sb + buf * 32768;
        #pragma unroll
        for (int i = 0; i < 4; i++) {
            int idx = i * 512 + tid;
            int half = idx >> 10, j = idx & 1023, n = j >> 3, q = j & 7;
            cpa16(base + half * 16384 + SWZ((uint32_t)(n * 128 + q * 16)),
                  (half ? g_W2l : g_W2h) + (size_t)n * 256 + c * 64 + q * 8);
        }
    };

    float C[8][4] = {};
    loadB1(0, 0); loadA1(0, 0); cpcommit();
    for (int c = 0; c < 8; c++) {
        const int buf = c & 1;
        if (c + 1 < 8) { loadB1(c + 1, buf ^ 1); loadA1(c + 1, buf ^ 1); cpcommit(); cpwait1(); }
        else cpwait0();
        __syncthreads();
        const uint32_t aH = sb + buf * 16384, aL = aH + 8192;
        const uint32_t bH = sb + 65536 + buf * 65536, bL = bH + 32768;
        #pragma unroll
        for (int k16 = 0; k16 < 4; k16++) {
            const int k0 = k16 * 16;
            uint32_t ah[4], al[4];
            const uint32_t o = SWZ((uint32_t)((wm * 16 + (lane & 15)) * 128 + k0 * 2 + (lane >> 4) * 16));
            ldsm4(ah, aH + o);
            ldsm4(al, aL + o);
            #pragma unroll
            for (int j = 0; j < 4; j++) {
                const int brow = wn * 64 + j * 16 + ((lane >> 4) << 3) + (lane & 7);
                const uint32_t bo = SWZ((uint32_t)(brow * 128 + (k0 + ((lane >> 3) & 1) * 8) * 2));
                uint32_t bh[4], bl[4];
                ldsm4(bh, bH + bo);
                ldsm4(bl, bL + bo);
                mma16816(C[2 * j], ah, bh); mma16816(C[2 * j + 1], ah, bh + 2);
                mma16816(C[2 * j], al, bh); mma16816(C[2 * j + 1], al, bh + 2);
                mma16816(C[2 * j], ah, bl); mma16816(C[2 * j + 1], ah, bl + 2);
            }
        }
        __syncthreads();
    }

    loadB2(0, 0); cpcommit();
    loadB2(1, 1); cpcommit();
    {
        const int rloc = wm * 16 + (lane >> 2);
        #pragma unroll
        for (int j8 = 0; j8 < 8; j8++) {
            const int n0 = wn * 64 + j8 * 8 + (lane & 3) * 2;
            float2 bb = *(const float2*)(b1 + n0);
            float v0 = fmaxf(C[j8][0] + bb.x, 0.f), v1 = fmaxf(C[j8][1] + bb.y, 0.f);
            float v2 = fmaxf(C[j8][2] + bb.x, 0.f), v3 = fmaxf(C[j8][3] + bb.y, 0.f);
            uint32_t h01, l01, h23, l23;
            split2(v0, v1, h01, l01); split2(v2, v3, h23, l23);
            const uint32_t cbase = 65536 + (n0 >> 6) * 8192;
            const uint32_t o1 = SWZ((uint32_t)(rloc * 128 + (n0 & 63) * 2));
            const uint32_t o2 = SWZ((uint32_t)((rloc + 8) * 128 + (n0 & 63) * 2));
            *(uint32_t*)(smem + cbase + o1)         = h01;
            *(uint32_t*)(smem + cbase + 65536 + o1) = l01;
            *(uint32_t*)(smem + cbase + o2)         = h23;
            *(uint32_t*)(smem + cbase + 65536 + o2) = l23;
        }
    }
    __syncthreads();

    float C2[4][4] = {};
    for (int c2 = 0; c2 < 4; c2++) {
        if (c2 < 3) cpwait1(); else cpwait0();
        __syncthreads();
        const uint32_t aH = sb + 65536 + c2 * 8192, aL = aH + 65536;
        const uint32_t bH = sb + (c2 & 1) * 32768,  bL = bH + 16384;
        #pragma unroll
        for (int k16 = 0; k16 < 4; k16++) {
            const int k0 = k16 * 16;
            uint32_t ah[4], al[4];
            const uint32_t o = SWZ((uint32_t)((wm * 16 + (lane & 15)) * 128 + k0 * 2 + (lane >> 4) * 16));
            ldsm4(ah, aH + o);
            ldsm4(al, aL + o);
            #pragma unroll
            for (int j = 0; j < 2; j++) {
                const int brow = wn * 32 + j * 16 + ((lane >> 4) << 3) + (lane & 7);
                const uint32_t bo = SWZ((uint32_t)(brow * 128 + (k0 + ((lane >> 3) & 1) * 8) * 2));
                uint32_t bh[4], bl[4];
                ldsm4(bh, bH + bo);
                ldsm4(bl, bL + bo);
                mma16816(C2[2 * j], ah, bh); mma16816(C2[2 * j + 1], ah, bh + 2);
                mma16816(C2[2 * j], al, bh); mma16816(C2[2 * j + 1], al, bh + 2);
                mma16816(C2[2 * j], ah, bl); mma16816(C2[2 * j + 1], ah, bl + 2);
            }
        }
        __syncthreads();
        if (c2 + 2 < 4) loadB2(c2 + 2, c2 & 1);
        cpcommit();
    }

    {
        const int r1 = m0 + wm * 16 + (lane >> 2);
        const int r2 = r1 + 8;
        const bool ok1 = (r1 - m0) < act, ok2 = (r2 - m0) < act;
        if (ok1 || ok2) {
            const int b1i = r1 >> lvl, j1 = (nl - 1) + (r1 & (nl - 1));
            const int b2i = r2 >> lvl, j2 = (nl - 1) + (r2 & (nl - 1));
            const size_t n1 = (size_t)(b1i * 63 + j1) * 128;
            const size_t n2 = (size_t)(b2i * 63 + j2) * 128;
            #pragma unroll
            for (int j8 = 0; j8 < 4; j8++) {
                const int n = wn * 32 + j8 * 8 + (lane & 3) * 2;
                float2 bb = *(const float2*)(b2 + n);
                float v0 = fmaxf(C2[j8][0] + bb.x, 0.f), v1 = fmaxf(C2[j8][1] + bb.y, 0.f);
                float v2 = fmaxf(C2[j8][2] + bb.x, 0.f), v3 = fmaxf(C2[j8][3] + bb.y, 0.f);
                uint32_t h01, l01, h23, l23;
                split2(v0, v1, h01, l01); split2(v2, v3, h23, l23);
                if (ok1) { *(uint32_t*)(g_reph + n1 + n) = h01; *(uint32_t*)(g_repl + n1 + n) = l01; }
                if (ok2) { *(uint32_t*)(g_reph + n2 + n) = h23; *(uint32_t*)(g_repl + n2 + n) = l23; }
            }
        }
    }
}

// Tail kernel: levels 2..0 fused, 8 batches/CTA, grid 256 (widened from 128).
// Active rows per level: l2=32, l1=16, l0=8 of a 64-row tile; act-guards
// prevent cross-CTA writes, clamped gather reads are harmless.
__global__ void __launch_bounds__(512, 1) tree_tail_kernel(
    const float* __restrict__ b1, const float* __restrict__ b2)
{
    extern __shared__ char smem[];
    const uint32_t sb = smem_u32(smem);
    const int tid = threadIdx.x, lane = tid & 31;
    const int wid = tid >> 5;
    const int wm = wid & 3, wn = wid >> 2;
    const int bat0 = blockIdx.x * 8;

    tree_body64(smem, sb, tid, lane, wm, wn, b1, b2, 2, bat0 * 4, 32);
    __syncthreads();
    tree_body64(smem, sb, tid, lane, wm, wn, b1, b2, 1, bat0 * 2, 16);
    __syncthreads();
    tree_body64(smem, sb, tid, lane, wm, wn, b1, b2, 0, bat0, 8);
}

// ============================================================
// Fused tree level (r10 verbatim), templated on MT. l5/l4 (128), l3 (64).
// ============================================================
template<int MT>
__global__ void __launch_bounds__(512, 1) tree_fused_kernel(
    const float* __restrict__ b1, const float* __restrict__ b2, int lvl, int nch)
{
    constexpr int TCNT = MT / 64;
    constexpr int ABUF = MT * 256;
    constexpr int WROW = MT / 4;
    extern __shared__ char smem[];
    const uint32_t sb = smem_u32(smem);
    const int tid = threadIdx.x, m0 = blockIdx.x * MT;
    const int wid = tid >> 5, lane = tid & 31;
    const int wm = wid & 3, wn = wid >> 2;
    const int nl = 1 << lvl;

    auto loadA1 = [&](int c, int buf) {
        const uint32_t base = sb + buf * ABUF;
        #pragma unroll
        for (int i = 0; i < (MT * 16) / 512; i++) {
            int idx = i * 512 + tid;
            int half = (idx >= MT * 8);
            int j = idx & (MT * 8 - 1);
            int row = j >> 3, q = j & 7;
            int lm = m0 + row, lb = lm >> lvl, lj = (nl - 1) + (lm & (nl - 1));
            const __nv_bfloat16* src;
            if (c < 4)      src = (half ? g_X1l : g_X1h) + (size_t)(lb * 63 + lj) * 256 + c * 64 + q * 8;
            else if (c < 6) src = (half ? g_repl : g_reph) + (size_t)(lb * 63 + 2 * lj + 1) * 128 + (c - 4) * 64 + q * 8;
            else            src = (half ? g_repl : g_reph) + (size_t)(lb * 63 + 2 * lj + 2) * 128 + (c - 6) * 64 + q * 8;
            cpa16(base + half * (MT * 128) + SWZ((uint32_t)(row * 128 + q * 16)), src);
        }
    };
    auto loadB1 = [&](int c, int buf) {
        const uint32_t base = sb + 65536 + buf * 65536;
        #pragma unroll
        for (int i = 0; i < 8; i++) {
            int idx = i * 512 + tid;
            int half = idx >> 11, j = idx & 2047, n = j >> 3, q = j & 7;
            cpa16(base + half * 32768 + SWZ((uint32_t)(n * 128 + q * 16)),
                  (half ? g_W1l : g_W1h) + (size_t)n * 512 + c * 64 + q * 8);
        }
    };
    auto loadB2 = [&](int c, int buf) {
        const uint32_t base = sb + buf * 32768;
        #pragma unroll
        for (int i = 0; i < 4; i++) {
            int idx = i * 512 + tid;
            int half = idx >> 10, j = idx & 1023, n = j >> 3, q = j & 7;
            cpa16(base + half * 16384 + SWZ((uint32_t)(n * 128 + q * 16)),
                  (half ? g_W2l : g_W2h) + (size_t)n * 256 + c * 64 + q * 8);
        }
    };

    float C[TCNT][8][4] = {};
    loadB1(0, 0); loadA1(0, 0); cpcommit();
    for (int c = 0; c < nch; c++) {
        const int buf = c & 1;
        if (c + 1 < nch) { loadB1(c + 1, buf ^ 1); loadA1(c + 1, buf ^ 1); cpcommit(); cpwait1(); }
        else cpwait0();
        __syncthreads();
        const uint32_t aH = sb + buf * ABUF, aL = aH + MT * 128;
        const uint32_t bH = sb + 65536 + buf * 65536, bL = bH + 32768;
        #pragma unroll
        for (int k16 = 0; k16 < 4; k16++) {
            const int k0 = k16 * 16;
            uint32_t ah[TCNT][4], al[TCNT][4];
            const uint32_t abase = (uint32_t)((wm * WROW + (lane & 15)) * 128 + k0 * 2 + (lane >> 4) * 16);
            #pragma unroll
            for (int t = 0; t < TCNT; t++) {
                uint32_t o = SWZ(abase + t * 2048);
                ldsm4(ah[t], aH + o);
                ldsm4(al[t], aL + o);
            }
            #pragma unroll
            for (int j = 0; j < 4; j++) {
                const int brow = wn * 64 + j * 16 + ((lane >> 4) << 3) + (lane & 7);
                const uint32_t bo = SWZ((uint32_t)(brow * 128 + (k0 + ((lane >> 3) & 1) * 8) * 2));
                uint32_t bh[4], bl[4];
                ldsm4(bh, bH + bo);
                ldsm4(bl, bL + bo);
                #pragma unroll
                for (int t = 0; t < TCNT; t++) { mma16816(C[t][2 * j], ah[t], bh); mma16816(C[t][2 * j + 1], ah[t], bh + 2); }
                #pragma unroll
                for (int t = 0; t < TCNT; t++) { mma16816(C[t][2 * j], al[t], bh); mma16816(C[t][2 * j + 1], al[t], bh + 2); }
                #pragma unroll
                for (int t = 0; t < TCNT; t++) { mma16816(C[t][2 * j], ah[t], bl); mma16816(C[t][2 * j + 1], ah[t], bl + 2); }
            }
        }
        __syncthreads();
    }

    loadB2(0, 0); cpcommit();
    loadB2(1, 1); cpcommit();
    #pragma unroll
    for (int t = 0; t < TCNT; t++) {
        const int rloc = wm * WROW + t * 16 + (lane >> 2);
        #pragma unroll
        for (int j8 = 0; j8 < 8; j8++) {
            const int n0 = wn * 64 + j8 * 8 + (lane & 3) * 2;
            float2 bb = *(const float2*)(b1 + n0);
            float v0 = fmaxf(C[t][j8][0] + bb.x, 0.f), v1 = fmaxf(C[t][j8][1] + bb.y, 0.f);
            float v2 = fmaxf(C[t][j8][2] + bb.x, 0.f), v3 = fmaxf(C[t][j8][3] + bb.y, 0.f);
            uint32_t h01, l01, h23, l23;
            split2(v0, v1, h01, l01); split2(v2, v3, h23, l23);
            const uint32_t cbase = 65536 + (n0 >> 6) * (MT * 128);
            const uint32_t o1 = SWZ((uint32_t)(rloc * 128 + (n0 & 63) * 2));
            const uint32_t o2 = SWZ((uint32_t)((rloc + 8) * 128 + (n0 & 63) * 2));
            *(uint32_t*)(smem + cbase + o1)         = h01;
            *(uint32_t*)(smem + cbase + 65536 + o1) = l01;
            *(uint32_t*)(smem + cbase + o2)         = h23;
            *(uint32_t*)(smem + cbase + 65536 + o2) = l23;
        }
    }
    __syncthreads();

    float C2[TCNT][4][4] = {};
    for (int c2 = 0; c2 < 4; c2++) {
        if (c2 < 3) cpwait1(); else cpwait0();
        __syncthreads();
        const uint32_t aH = sb + 65536 + c2 * (MT * 128), aL = aH + 65536;
        const uint32_t bH = sb + (c2 & 1) * 32768,        bL = bH + 16384;
        #pragma unroll
        for (int k16 = 0; k16 < 4; k16++) {
            const int k0 = k16 * 16;
            uint32_t ah[TCNT][4], al[TCNT][4];
            const uint32_t abase = (uint32_t)((wm * WROW + (lane & 15)) * 128 + k0 * 2 + (lane >> 4) * 16);
            #pragma unroll
            for (int t = 0; t < TCNT; t++) {
                uint32_t o = SWZ(abase + t * 2048);
                ldsm4(ah[t], aH + o);
                ldsm4(al[t], aL + o);
            }
            #pragma unroll
            for (int j = 0; j < 2; j++) {
                const int brow = wn * 32 + j * 16 + ((lane >> 4) << 3) + (lane & 7);
                const uint32_t bo = SWZ((uint32_t)(brow * 128 + (k0 + ((lane >> 3) & 1) * 8) * 2));
                uint32_t bh[4], bl[4];
                ldsm4(bh, bH + bo);
                ldsm4(bl, bL + bo);
                #pragma unroll
                for (int t = 0; t < TCNT; t++) { mma16816(C2[t][2 * j], ah[t], bh); mma16816(C2[t][2 * j + 1], ah[t], bh + 2); }
                #pragma unroll
                for (int t = 0; t < TCNT; t++) { mma16816(C2[t][2 * j], al[t], bh); mma16816(C2[t][2 * j + 1], al[t], bh + 2); }
                #pragma unroll
                for (int t = 0; t < TCNT; t++) { mma16816(C2[t][2 * j], ah[t], bl); mma16816(C2[t][2 * j + 1], ah[t], bl + 2); }
            }
        }
        __syncthreads();
        if (c2 + 2 < 4) loadB2(c2 + 2, c2 & 1);
        cpcommit();
    }

    #pragma unroll
    for (int t = 0; t < TCNT; t++) {
        const int r1 = m0 + wm * WROW + t * 16 + (lane >> 2);
        const int r2 = r1 + 8;
        const int b1i = r1 >> lvl, j1 = (nl - 1) + (r1 & (nl - 1));
        const int b2i = r2 >> lvl, j2 = (nl - 1) + (r2 & (nl - 1));
        const size_t n1 = (size_t)(b1i * 63 + j1) * 128;
        const size_t n2 = (size_t)(b2i * 63 + j2) * 128;
        #pragma unroll
        for (int j8 = 0; j8 < 4; j8++) {
            const int n = wn * 32 + j8 * 8 + (lane & 3) * 2;
            float2 bb = *(const float2*)(b2 + n);
            float v0 = fmaxf(C2[t][j8][0] + bb.x, 0.f), v1 = fmaxf(C2[t][j8][1] + bb.y, 0.f);
            float v2 = fmaxf(C2[t][j8][2] + bb.x, 0.f), v3 = fmaxf(C2[t][j8][3] + bb.y, 0.f);
            uint32_t h01, l01, h23, l23;
            split2(v0, v1, h01, l01); split2(v2, v3, h23, l23);
            *(uint32_t*)(g_reph + n1 + n) = h01; *(uint32_t*)(g_repl + n1 + n) = l01;
            *(uint32_t*)(g_reph + n2 + n) = h23; *(uint32_t*)(g_repl + n2 + n) = l23;
        }
    }
}

// ---- heads ----
__global__ void __launch_bounds__(128) heads_kernel(
    const float* __restrict__ Wc1, const float* __restrict__ bc1,
    const float* __restrict__ Wc2, const float* __restrict__ bc2,
    const float* __restrict__ Wc3, const float* __restrict__ bc3,
    const float* __restrict__ Wd1, const float* __restrict__ bd1,
    const float* __restrict__ Wd2, const float* __restrict__ bd2,
    const float* __restrict__ Wd3, const float* __restrict__ bd3,
    float* __restrict__ out)
{
    __shared__ float sroot[128];
    __shared__ float sh1[128];
    __shared__ float sprod[128];
    int b = blockIdx.x, t = threadIdx.x;
    size_t ro = (size_t)(b * 63) * 128 + t;
    sroot[t] = __bfloat162float(g_reph[ro]) + __bfloat162float(g_repl[ro]);
    __syncthreads();

    int head = t >> 6, c = t & 63;
    const float* W1 = head ? Wd1 : Wc1; const float* B1 = head ? bd1 : bc1;
    const float* W2 = head ? Wd2 : Wc2; const float* B2 = head ? bd2 : bc2;
    const float* W3 = head ? Wd3 : Wc3; const float* B3 = head ? bd3 : bc3;

    float h = B1[c];
    #pragma unroll 8
    for (int k = 0; k < 128; k++) h += sroot[k] * W1[k * 64 + c];
    sh1[t] = fmaxf(h, 0.f);
    __syncthreads();

    float h2 = B2[c];
    #pragma unroll 8
    for (int k = 0; k < 64; k++) h2 += sh1[head * 64 + k] * W2[k * 64 + c];
    h2 = fmaxf(h2, 0.f);
    sprod[t] = h2 * W3[c];
    __syncthreads();

    if (c == 0) {
        float s = B3[0];
        #pragma unroll 8
        for (int k = 0; k < 64; k++) s += sprod[head * 64 + k];
        out[head * BSZ + b] = 1.f / (1.f + expf(-s));
    }
}

// ---- launch ----
#define SM_TREE 196608
#define SM_IN   65536

extern "C" void kernel_launch(void* const* d_in, const int* in_sizes, int n_in,
                              void* d_out, int out_size)
{
    const float* op      = (const float*)d_in[0];
    const float* extra   = (const float*)d_in[1];
    const float* cond1   = (const float*)d_in[2];
    const float* cond2   = (const float*)d_in[3];
    const float* bitmap  = (const float*)d_in[4];
    const float* hascond = (const float*)d_in[5];
    const float* W_op = (const float*)d_in[6];   const float* b_op = (const float*)d_in[7];
    const float* W_pr = (const float*)d_in[8];   const float* b_pr = (const float*)d_in[9];
    const float* W_bm = (const float*)d_in[10];  const float* b_bm = (const float*)d_in[11];
    const float* W_r1 = (const float*)d_in[12];  const float* b_r1 = (const float*)d_in[13];
    const float* W_r2 = (const float*)d_in[14];  const float* b_r2 = (const float*)d_in[15];
    const float* W_c1 = (const float*)d_in[16];  const float* b_c1 = (const float*)d_in[17];
    const float* W_c2 = (const float*)d_in[18];  const float* b_c2 = (const float*)d_in[19];
    const float* W_c3 = (const float*)d_in[20];  const float* b_c3 = (const float*)d_in[21];
    const float* W_d1 = (const float*)d_in[22];  const float* b_d1 = (const float*)d_in[23];
    const float* W_d2 = (const float*)d_in[24];  const float* b_d2 = (const float*)d_in[25];
    const float* W_d3 = (const float*)d_in[26];  const float* b_d3 = (const float*)d_in[27];

    cudaFuncSetAttribute(tree_fused_kernel<128>, cudaFuncAttributeMaxDynamicSharedMemorySize, SM_TREE);
    cudaFuncSetAttribute(tree_fused_kernel<64>,  cudaFuncAttributeMaxDynamicSharedMemorySize, SM_TREE);
    cudaFuncSetAttribute(tree_tail_kernel,       cudaFuncAttributeMaxDynamicSharedMemorySize, SM_TREE);
    cudaFuncSetAttribute(input_kernel,           cudaFuncAttributeMaxDynamicSharedMemorySize, SM_IN);

    prep_kernel<<<928, 256>>>(W_r1, W_r2, W_bm, W_op, W_pr);
    input_kernel<<<NROWS / 64, 256, SM_IN>>>(op, extra, cond1, cond2, bitmap, hascond,
                                             b_op, b_pr, b_bm);

    tree_fused_kernel<128><<<(BSZ << 5) / 128, 512, SM_TREE>>>(b_r1, b_r2, 5, 4);
    tree_fused_kernel<128><<<(BSZ << 4) / 128, 512, SM_TREE>>>(b_r1, b_r2, 4, 8);
    tree_fused_kernel<64> <<<(BSZ << 3) / 64,  512, SM_TREE>>>(b_r1, b_r2, 3, 8);
    tree_tail_kernel<<<BSZ / 8, 512, SM_TREE>>>(b_r1, b_r2);

    heads_kernel<<<BSZ, 128>>>(W_c1, b_c1, W_c2, b_c2, W_c3, b_c3,
                               W_d1, b_d1, W_d2, b_d2, W_d3, b_d3,
                               (float*)d_out);
}

// round 13
// speedup vs baseline: 1.1303x; 1.1303x over previous
#include <cuda_runtime.h>
#include <cuda_bf16.h>
#include <cstdint>
#include <math.h>

#define BSZ   2048
#define NROWS (BSZ * 63)   // 129024

// ---- scratch (pre-split bf16 hi/lo activations) ----
__device__ __nv_bfloat16 g_X1h[(size_t)NROWS * 256], g_X1l[(size_t)NROWS * 256];
__device__ __nv_bfloat16 g_reph[(size_t)NROWS * 128], g_repl[(size_t)NROWS * 128];

// split-bf16 weights, transposed to [N][K]
__device__ __nv_bfloat16 g_W1h[256 * 512],  g_W1l[256 * 512];
__device__ __nv_bfloat16 g_W2h[128 * 256],  g_W2l[128 * 256];
__device__ __nv_bfloat16 g_Wbmh[64 * 1024], g_Wbml[64 * 1024];
__device__ __nv_bfloat16 g_Woph[64 * 64],   g_Wopl[64 * 64];
__device__ __nv_bfloat16 g_Wprh[64 * 64],   g_Wprl[64 * 64];

// ---- helpers ----
#define SWZ(o) ((o) ^ (((o) >> 3) & 0x70))

__device__ __forceinline__ uint32_t smem_u32(const void* p) {
    uint32_t a;
    asm("{ .reg .u64 t; cvta.to.shared.u64 t, %1; cvt.u32.u64 %0, t; }" : "=r"(a) : "l"(p));
    return a;
}
__device__ __forceinline__ void ldsm4(uint32_t* r, uint32_t addr) {
    asm volatile("ldmatrix.sync.aligned.m8n8.x4.shared.b16 {%0,%1,%2,%3}, [%4];"
                 : "=r"(r[0]), "=r"(r[1]), "=r"(r[2]), "=r"(r[3]) : "r"(addr));
}
__device__ __forceinline__ void mma16816(float* c, const uint32_t* a, const uint32_t* b) {
    asm volatile("mma.sync.aligned.m16n8k16.row.col.f32.bf16.bf16.f32 "
                 "{%0,%1,%2,%3}, {%4,%5,%6,%7}, {%8,%9}, {%0,%1,%2,%3};"
                 : "+f"(c[0]), "+f"(c[1]), "+f"(c[2]), "+f"(c[3])
                 : "r"(a[0]), "r"(a[1]), "r"(a[2]), "r"(a[3]), "r"(b[0]), "r"(b[1]));
}
__device__ __forceinline__ void cpa16(uint32_t dst, const void* src) {
    asm volatile("cp.async.cg.shared.global [%0], [%1], 16;" :: "r"(dst), "l"(src) : "memory");
}
__device__ __forceinline__ void cpcommit() { asm volatile("cp.async.commit_group;" ::: "memory"); }
__device__ __forceinline__ void cpwait0()  { asm volatile("cp.async.wait_group 0;" ::: "memory"); }
__device__ __forceinline__ void cpwait1()  { asm volatile("cp.async.wait_group 1;" ::: "memory"); }

__device__ __forceinline__ void split2(float x, float y, uint32_t& hi, uint32_t& lo) {
    float2 f = make_float2(x, y);
    __nv_bfloat162 h = __float22bfloat162_rn(f);
    float2 r = make_float2(x - __bfloat162float(h.x), y - __bfloat162float(h.y));
    __nv_bfloat162 l = __float22bfloat162_rn(r);
    hi = *reinterpret_cast<uint32_t*>(&h);
    lo = *reinterpret_cast<uint32_t*>(&l);
}
__device__ __forceinline__ void splitw(float v, __nv_bfloat16* ph, __nv_bfloat16* pl) {
    __nv_bfloat16 h = __float2bfloat16(v);
    *ph = h;
    *pl = __float2bfloat16(v - __bfloat162float(h));
}

// ---- weight prep ----
__global__ void __launch_bounds__(256) prep_kernel(
    const float* __restrict__ W1, const float* __restrict__ W2,
    const float* __restrict__ Wbm, const float* __restrict__ Wop,
    const float* __restrict__ Wpr)
{
    int idx = blockIdx.x * 256 + threadIdx.x;
    if (idx < 131072) { int n = idx >> 9, k = idx & 511;
        splitw(W1[k * 256 + n], &g_W1h[idx], &g_W1l[idx]); return; }
    idx -= 131072;
    if (idx < 32768) { int n = idx >> 8, k = idx & 255;
        splitw(W2[k * 128 + n], &g_W2h[idx], &g_W2l[idx]); return; }
    idx -= 32768;
    if (idx < 65536) { int n = idx >> 10, k = idx & 1023;
        float v = (k < 1000) ? Wbm[k * 64 + n] : 0.f;
        splitw(v, &g_Wbmh[idx], &g_Wbml[idx]); return; }
    idx -= 65536;
    if (idx < 4096) { int n = idx >> 6, k = idx & 63;
        splitw(Wop[k * 64 + n], &g_Woph[idx], &g_Wopl[idx]); return; }
    idx -= 4096;
    if (idx < 4096) { int n = idx >> 6, k = idx & 63;
        splitw(Wpr[k * 64 + n], &g_Wprh[idx], &g_Wprl[idx]); }
}

// ============================================================
// Input kernel v4 (r10 proven): M=64 rows/CTA, 256 threads, 3 CTAs/SM.
// ============================================================
__global__ void __launch_bounds__(256, 3) input_kernel(
    const float* __restrict__ op, const float* __restrict__ extra,
    const float* __restrict__ c1, const float* __restrict__ c2,
    const float* __restrict__ bm, const float* __restrict__ hc,
    const float* __restrict__ bop, const float* __restrict__ bpr,
    const float* __restrict__ bbm)
{
    extern __shared__ char smem[];
    const uint32_t sb = smem_u32(smem);
    const int tid = threadIdx.x, m0 = blockIdx.x * 64;
    const int wid = tid >> 5, lane = tid & 31;
    const int wm = wid & 3, wn = wid >> 2;   // 4m x 2n

    float4 pre[4];
    auto loadA_regs = [&](int s) {
        #pragma unroll
        for (int i = 0; i < 4; i++) {
            int idx = i * 256 + tid;
            int row = idx >> 4, q4 = idx & 15;
            float4 v = make_float4(0.f, 0.f, 0.f, 0.f);
            if (s == 0) {
                int kl = q4 * 4;
                v = (kl < 32) ? *(const float4*)(op    + (size_t)(m0 + row) * 32 + kl)
                              : *(const float4*)(extra + (size_t)(m0 + row) * 32 + kl - 32);
            } else if (s == 1) {
                v = *(const float4*)(c1 + (size_t)(m0 + row) * 64 + q4 * 4);
            } else if (s == 2) {
                v = *(const float4*)(c2 + (size_t)(m0 + row) * 64 + q4 * 4);
            } else {
                int kg4 = (s - 3) * 16 + q4;
                if (kg4 < 250) v = *(const float4*)(bm + (size_t)(m0 + row) * 1000 + kg4 * 4);
            }
            pre[i] = v;
        }
    };
    auto loadB = [&](int s) {
        const int st = s & 1;
        const __nv_bfloat16 *Wh, *Wl;
        int stride, koff;
        if (s == 0)      { Wh = g_Woph; Wl = g_Wopl; stride = 64;   koff = 0; }
        else if (s <= 2) { Wh = g_Wprh; Wl = g_Wprl; stride = 64;   koff = 0; }
        else             { Wh = g_Wbmh; Wl = g_Wbml; stride = 1024; koff = (s - 3) * 64; }
        #pragma unroll
        for (int i = 0; i < 4; i++) {
            int idx = i * 256 + tid;
            int half = idx >> 9, j = idx & 511, n = j >> 3, q = j & 7;
            cpa16(sb + 32768 + st * 16384 + half * 8192 + SWZ((uint32_t)(n * 128 + q * 16)),
                  (half ? Wl : Wh) + (size_t)n * stride + koff + q * 8);
        }
    };

    float C[2][2][4] = {};
    loadA_regs(0);
    loadB(0); cpcommit();

    for (int s = 0; s < 19; s++) {
        const int st = s & 1;
        __syncthreads();
        #pragma unroll
        for (int i = 0; i < 4; i++) {
            int idx = i * 256 + tid;
            int row = idx >> 4, q4 = idx & 15;
            uint32_t h0, l0, h1, l1;
            split2(pre[i].x, pre[i].y, h0, l0);
            split2(pre[i].z, pre[i].w, h1, l1);
            uint32_t o = SWZ((uint32_t)(row * 128 + q4 * 8));
            *(uint2*)(smem + st * 16384 + o)        = make_uint2(h0, h1);
            *(uint2*)(smem + st * 16384 + 8192 + o) = make_uint2(l0, l1);
        }
        if (s + 1 < 19) { loadA_regs(s + 1); loadB(s + 1); }
        cpcommit();
        cpwait1();
        __syncthreads();

        const uint32_t aH = sb + st * 16384, aL = aH + 8192;
        const uint32_t bH = sb + 32768 + st * 16384, bL = bH + 8192;
        #pragma unroll
        for (int k16 = 0; k16 < 4; k16++) {
            const int k0 = k16 * 16;
            uint32_t ah[4], al[4];
            const uint32_t o = SWZ((uint32_t)((wm * 16 + (lane & 15)) * 128 + k0 * 2 + (lane >> 4) * 16));
            ldsm4(ah, aH + o);
            ldsm4(al, aL + o);
            uint32_t bh[2][4], bl[2][4];
            #pragma unroll
            for (int j = 0; j < 2; j++) {
                const int brow = wn * 32 + j * 16 + ((lane >> 4) << 3) + (lane & 7);
                const uint32_t bo = SWZ((uint32_t)(brow * 128 + (k0 + ((lane >> 3) & 1) * 8) * 2));
                ldsm4(bh[j], bH + bo);
                ldsm4(bl[j], bL + bo);
            }
            #pragma unroll
            for (int j = 0; j < 2; j++) { mma16816(C[j][0], ah, bh[j]); mma16816(C[j][1], ah, bh[j] + 2); }
            #pragma unroll
            for (int j = 0; j < 2; j++) { mma16816(C[j][0], al, bh[j]); mma16816(C[j][1], al, bh[j] + 2); }
            #pragma unroll
            for (int j = 0; j < 2; j++) { mma16816(C[j][0], ah, bl[j]); mma16816(C[j][1], ah, bl[j] + 2); }
        }

        if (s <= 2 || s == 18) {
            const int colbase = (s <= 2) ? s * 64 : 192;
            const float* bias = (s == 0) ? bop : (s <= 2 ? bpr : bbm);
            const bool isbm = (s == 18);
            const int r1 = m0 + wm * 16 + (lane >> 2);
            const int r2 = r1 + 8;
            float hv1 = 1.f, hv2 = 1.f;
            if (isbm) { hv1 = hc[r1]; hv2 = hc[r2]; }
            #pragma unroll
            for (int j = 0; j < 2; j++)
                #pragma unroll
                for (int h8 = 0; h8 < 2; h8++) {
                    const int n = wn * 32 + j * 16 + h8 * 8 + (lane & 3) * 2;
                    float2 bb = *(const float2*)(bias + n);
                    float v0 = (C[j][h8][0] + bb.x) * hv1, v1 = (C[j][h8][1] + bb.y) * hv1;
                    float v2 = (C[j][h8][2] + bb.x) * hv2, v3 = (C[j][h8][3] + bb.y) * hv2;
                    uint32_t h01, l01, h23, l23;
                    split2(v0, v1, h01, l01); split2(v2, v3, h23, l23);
                    size_t o1 = (size_t)r1 * 256 + colbase + n;
                    size_t o2 = (size_t)r2 * 256 + colbase + n;
                    *(uint32_t*)(g_X1h + o1) = h01; *(uint32_t*)(g_X1l + o1) = l01;
                    *(uint32_t*)(g_X1h + o2) = h23; *(uint32_t*)(g_X1l + o2) = l23;
                    #pragma unroll
                    for (int q = 0; q < 4; q++) C[j][h8][q] = 0.f;
                }
        }
    }
}

// ============================================================
// NEW: leaf-level (l5) kernel, 256 threads, 2 CTAs/SM, 96KB SMEM.
// K=256 pure-X1 A (children zero). Single-buffered loads; occ-2 hides.
// SMEM: A hi 8K @0, lo 8K @8192 | B1 hi 32K @32768, lo 32K @65536
//   (phase2: H hi 4x8K @32768, lo @65536; B2 hi 16K @0, lo 16K @16384)
// ============================================================
__global__ void __launch_bounds__(256, 2) l5_kernel(
    const float* __restrict__ b1, const float* __restrict__ b2)
{
    extern __shared__ char smem[];
    const uint32_t sb = smem_u32(smem);
    const int tid = threadIdx.x, lane = tid & 31, wid = tid >> 5;
    const int wm = wid & 3, wn = wid >> 2;   // 4m x 2n
    const int m0 = blockIdx.x * 64;

    // ---- phase 1: H = relu(X1 @ W1 + b1) over K=256 ----
    float C[16][4] = {};
    for (int c = 0; c < 4; c++) {
        __syncthreads();   // protect A/B from prior readers
        {
            int row = tid >> 2;
            int lm = m0 + row;
            size_t node = (size_t)((lm >> 5) * 63 + 31 + (lm & 31)) * 256 + c * 64;
            #pragma unroll
            for (int i = 0; i < 2; i++) {
                int q = (tid & 3) * 2 + i;
                uint32_t o = SWZ((uint32_t)(row * 128 + q * 16));
                cpa16(sb + o,        g_X1h + node + q * 8);
                cpa16(sb + 8192 + o, g_X1l + node + q * 8);
            }
        }
        #pragma unroll
        for (int i = 0; i < 8; i++) {
            int idx = i * 256 + tid;
            int n = idx >> 3, q = idx & 7;
            uint32_t o = SWZ((uint32_t)(n * 128 + q * 16));
            cpa16(sb + 32768 + o, g_W1h + (size_t)n * 512 + c * 64 + q * 8);
            cpa16(sb + 65536 + o, g_W1l + (size_t)n * 512 + c * 64 + q * 8);
        }
        cpcommit(); cpwait0();
        __syncthreads();

        #pragma unroll
        for (int k16 = 0; k16 < 4; k16++) {
            const int k0 = k16 * 16;
            uint32_t ah[4], al[4];
            const uint32_t o = SWZ((uint32_t)((wm * 16 + (lane & 15)) * 128 + k0 * 2 + (lane >> 4) * 16));
            ldsm4(ah, sb + o);
            ldsm4(al, sb + 8192 + o);
            #pragma unroll
            for (int j = 0; j < 8; j++) {
                const int brow = wn * 128 + j * 16 + ((lane >> 4) << 3) + (lane & 7);
                const uint32_t bo = SWZ((uint32_t)(brow * 128 + (k0 + ((lane >> 3) & 1) * 8) * 2));
                uint32_t bh[4], bl[4];
                ldsm4(bh, sb + 32768 + bo);
                ldsm4(bl, sb + 65536 + bo);
                mma16816(C[2 * j],     ah, bh); mma16816(C[2 * j + 1], ah, bh + 2);
                mma16816(C[2 * j],     al, bh); mma16816(C[2 * j + 1], al, bh + 2);
                mma16816(C[2 * j],     ah, bl); mma16816(C[2 * j + 1], ah, bl + 2);
            }
        }
    }
    __syncthreads();   // all B1 readers done; region becomes H

    // H (relu + split) -> panels: hi @32768 + p*8192, lo @65536 + p*8192
    {
        const int rloc = wm * 16 + (lane >> 2);
        #pragma unroll
        for (int j8 = 0; j8 < 16; j8++) {
            const int n0 = wn * 128 + j8 * 8 + (lane & 3) * 2;
            float2 bb = *(const float2*)(b1 + n0);
            float v0 = fmaxf(C[j8][0] + bb.x, 0.f), v1 = fmaxf(C[j8][1] + bb.y, 0.f);
            float v2 = fmaxf(C[j8][2] + bb.x, 0.f), v3 = fmaxf(C[j8][3] + bb.y, 0.f);
            uint32_t h01, l01, h23, l23;
            split2(v0, v1, h01, l01); split2(v2, v3, h23, l23);
            const uint32_t pb = (uint32_t)(n0 >> 6) * 8192;
            const uint32_t o1 = SWZ((uint32_t)(rloc * 128 + (n0 & 63) * 2));
            const uint32_t o2 = SWZ((uint32_t)((rloc + 8) * 128 + (n0 & 63) * 2));
            *(uint32_t*)(smem + 32768 + pb + o1) = h01;
            *(uint32_t*)(smem + 65536 + pb + o1) = l01;
            *(uint32_t*)(smem + 32768 + pb + o2) = h23;
            *(uint32_t*)(smem + 65536 + pb + o2) = l23;
        }
    }

    // ---- phase 2: rep = relu(H @ W2 + b2) over K=256 ----
    float C2[8][4] = {};
    for (int c2 = 0; c2 < 4; c2++) {
        __syncthreads();   // orders H writes (c2=0) / protects B2 (c2>0)
        #pragma unroll
        for (int i = 0; i < 4; i++) {
            int idx = i * 256 + tid;
            int n = idx >> 3, q = idx & 7;
            uint32_t o = SWZ((uint32_t)(n * 128 + q * 16));
            cpa16(sb + o,         g_W2h + (size_t)n * 256 + c2 * 64 + q * 8);
            cpa16(sb + 16384 + o, g_W2l + (size_t)n * 256 + c2 * 64 + q * 8);
        }
        cpcommit(); cpwait0();
        __syncthreads();

        const uint32_t aH = sb + 32768 + c2 * 8192, aL = sb + 65536 + c2 * 8192;
        #pragma unroll
        for (int k16 = 0; k16 < 4; k16++) {
            const int k0 = k16 * 16;
            uint32_t ah[4], al[4];
            const uint32_t o = SWZ((uint32_t)((wm * 16 + (lane & 15)) * 128 + k0 * 2 + (lane >> 4) * 16));
            ldsm4(ah, aH + o);
            ldsm4(al, aL + o);
            #pragma unroll
            for (int j = 0; j < 4; j++) {
                const int brow = wn * 64 + j * 16 + ((lane >> 4) << 3) + (lane & 7);
                const uint32_t bo = SWZ((uint32_t)(brow * 128 + (k0 + ((lane >> 3) & 1) * 8) * 2));
                uint32_t bh[4], bl[4];
                ldsm4(bh, sb + bo);
                ldsm4(bl, sb + 16384 + bo);
                mma16816(C2[2 * j],     ah, bh); mma16816(C2[2 * j + 1], ah, bh + 2);
                mma16816(C2[2 * j],     al, bh); mma16816(C2[2 * j + 1], al, bh + 2);
                mma16816(C2[2 * j],     ah, bl); mma16816(C2[2 * j + 1], ah, bl + 2);
            }
        }
    }

    // epilogue: scatter leaf reps
    {
        const int r1 = m0 + wm * 16 + (lane >> 2);
        const int r2 = r1 + 8;
        const size_t n1 = (size_t)((r1 >> 5) * 63 + 31 + (r1 & 31)) * 128;
        const size_t n2 = (size_t)((r2 >> 5) * 63 + 31 + (r2 & 31)) * 128;
        #pragma unroll
        for (int j8 = 0; j8 < 8; j8++) {
            const int n = wn * 64 + j8 * 8 + (lane & 3) * 2;
            float2 bb = *(const float2*)(b2 + n);
            float v0 = fmaxf(C2[j8][0] + bb.x, 0.f), v1 = fmaxf(C2[j8][1] + bb.y, 0.f);
            float v2 = fmaxf(C2[j8][2] + bb.x, 0.f), v3 = fmaxf(C2[j8][3] + bb.y, 0.f);
            uint32_t h01, l01, h23, l23;
            split2(v0, v1, h01, l01); split2(v2, v3, h23, l23);
            *(uint32_t*)(g_reph + n1 + n) = h01; *(uint32_t*)(g_repl + n1 + n) = l01;
            *(uint32_t*)(g_reph + n2 + n) = h23; *(uint32_t*)(g_repl + n2 + n) = l23;
        }
    }
}

// ============================================================
// Tree level body, MT=64, 512 threads (4m x 4n), act-guarded. (r10 verbatim)
// ============================================================
__device__ __forceinline__ void tree_body64(
    char* smem, uint32_t sb, int tid, int lane, int wm, int wn,
    const float* b1, const float* b2, int lvl, int m0, int act)
{
    const int nl = 1 << lvl;
    const int lmax = (BSZ << lvl) - 1;

    auto loadA1 = [&](int c, int buf) {
        const uint32_t base = sb + buf * 16384;
        int row = tid >> 3, q = tid & 7;
        int lm = m0 + row; if (lm > lmax) lm = lmax;
        int lb = lm >> lvl, lj = (nl - 1) + (lm & (nl - 1));
        const __nv_bfloat16* src;
        if (c < 4)      src = g_X1h + (size_t)(lb * 63 + lj) * 256 + c * 64 + q * 8;
        else if (c < 6) src = g_reph + (size_t)(lb * 63 + 2 * lj + 1) * 128 + (c - 4) * 64 + q * 8;
        else            src = g_reph + (size_t)(lb * 63 + 2 * lj + 2) * 128 + (c - 6) * 64 + q * 8;
        cpa16(base + SWZ((uint32_t)(row * 128 + q * 16)), src);
        if (c < 4)      src = g_X1l + (size_t)(lb * 63 + lj) * 256 + c * 64 + q * 8;
        else if (c < 6) src = g_repl + (size_t)(lb * 63 + 2 * lj + 1) * 128 + (c - 4) * 64 + q * 8;
        else            src = g_repl + (size_t)(lb * 63 + 2 * lj + 2) * 128 + (c - 6) * 64 + q * 8;
        cpa16(base + 8192 + SWZ((uint32_t)(row * 128 + q * 16)), src);
    };
    auto loadB1 = [&](int c, int buf) {
        const uint32_t base = sb + 65536 + buf * 65536;
        #pragma unroll
        for (int i = 0; i < 8; i++) {
            int idx = i * 512 + tid;
            int half = idx >> 11, j = idx & 2047, n = j >> 3, q = j & 7;
            cpa16(base + half * 32768 + SWZ((uint32_t)(n * 128 + q * 16)),
                  (half ? g_W1l : g_W1h) + (size_t)n * 512 + c * 64 + q * 8);
        }
    };
    auto loadB2 = [&](int c, int buf) {
        const uint32_t base = sb + buf * 32768;
        #pragma unroll
        for (int i = 0; i < 4; i++) {
            int idx = i * 512 + tid;
            int half = idx >> 10, j = idx & 1023, n = j >> 3, q = j & 7;
            cpa16(base + half * 16384 + SWZ((uint32_t)(n * 128 + q * 16)),
                  (half ? g_W2l : g_W2h) + (size_t)n * 256 + c * 64 + q * 8);
        }
    };

    float C[8][4] = {};
    loadB1(0, 0); loadA1(0, 0); cpcommit();
    for (int c = 0; c < 8; c++) {
        const int buf = c & 1;
        if (c + 1 < 8) { loadB1(c + 1, buf ^ 1); loadA1(c + 1, buf ^ 1); cpcommit(); cpwait1(); }
        else cpwait0();
        __syncthreads();
        const uint32_t aH = sb + buf * 16384, aL = aH + 8192;
        const uint32_t bH = sb + 65536 + buf * 65536, bL = bH + 32768;
        #pragma unroll
        for (int k16 = 0; k16 < 4; k16++) {
            const int k0 = k16 * 16;
            uint32_t ah[4], al[4];
            const uint32_t o = SWZ((uint32_t)((wm * 16 + (lane & 15)) * 128 + k0 * 2 + (lane >> 4) * 16));
            ldsm4(ah, aH + o);
            ldsm4(al, aL + o);
            #pragma unroll
            for (int j = 0; j < 4; j++) {
                const int brow = wn * 64 + j * 16 + ((lane >> 4) << 3) + (lane & 7);
                const uint32_t bo = SWZ((uint32_t)(brow * 128 + (k0 + ((lane >> 3) & 1) * 8) * 2));
                uint32_t bh[4], bl[4];
                ldsm4(bh, bH + bo);
                ldsm4(bl, bL + bo);
                mma16816(C[2 * j], ah, bh); mma16816(C[2 * j + 1], ah, bh + 2);
                mma16816(C[2 * j], al, bh); mma16816(C[2 * j + 1], al, bh + 2);
                mma16816(C[2 * j], ah, bl); mma16816(C[2 * j + 1], ah, bl + 2);
            }
        }
        __syncthreads();
    }

    loadB2(0, 0); cpcommit();
    loadB2(1, 1); cpcommit();
    {
        const int rloc = wm * 16 + (lane >> 2);
        #pragma unroll
        for (int j8 = 0; j8 < 8; j8++) {
            const int n0 = wn * 64 + j8 * 8 + (lane & 3) * 2;
            float2 bb = *(const float2*)(b1 + n0);
            float v0 = fmaxf(C[j8][0] + bb.x, 0.f), v1 = fmaxf(C[j8][1] + bb.y, 0.f);
            float v2 = fmaxf(C[j8][2] + bb.x, 0.f), v3 = fmaxf(C[j8][3] + bb.y, 0.f);
            uint32_t h01, l01, h23, l23;
            split2(v0, v1, h01, l01); split2(v2, v3, h23, l23);
            const uint32_t cbase = 65536 + (n0 >> 6) * 8192;
            const uint32_t o1 = SWZ((uint32_t)(rloc * 128 + (n0 & 63) * 2));
            const uint32_t o2 = SWZ((uint32_t)((rloc + 8) * 128 + (n0 & 63) * 2));
            *(uint32_t*)(smem + cbase + o1)         = h01;
            *(uint32_t*)(smem + cbase + 65536 + o1) = l01;
            *(uint32_t*)(smem + cbase + o2)         = h23;
            *(uint32_t*)(smem + cbase + 65536 + o2) = l23;
        }
    }
    __syncthreads();

    float C2[4][4] = {};
    for (int c2 = 0; c2 < 4; c2++) {
        if (c2 < 3) cpwait1(); else cpwait0();
        __syncthreads();
        const uint32_t aH = sb + 65536 + c2 * 8192, aL = aH + 65536;
        const uint32_t bH = sb + (c2 & 1) * 32768,  bL = bH + 16384;
        #pragma unroll
        for (int k16 = 0; k16 < 4; k16++) {
            const int k0 = k16 * 16;
            uint32_t ah[4], al[4];
            const uint32_t o = SWZ((uint32_t)((wm * 16 + (lane & 15)) * 128 + k0 * 2 + (lane >> 4) * 16));
            ldsm4(ah, aH + o);
            ldsm4(al, aL + o);
            #pragma unroll
            for (int j = 0; j < 2; j++) {
                const int brow = wn * 32 + j * 16 + ((lane >> 4) << 3) + (lane & 7);
                const uint32_t bo = SWZ((uint32_t)(brow * 128 + (k0 + ((lane >> 3) & 1) * 8) * 2));
                uint32_t bh[4], bl[4];
                ldsm4(bh, bH + bo);
                ldsm4(bl, bL + bo);
                mma16816(C2[2 * j], ah, bh); mma16816(C2[2 * j + 1], ah, bh + 2);
                mma16816(C2[2 * j], al, bh); mma16816(C2[2 * j + 1], al, bh + 2);
                mma16816(C2[2 * j], ah, bl); mma16816(C2[2 * j + 1], ah, bl + 2);
            }
        }
        __syncthreads();
        if (c2 + 2 < 4) loadB2(c2 + 2, c2 & 1);
        cpcommit();
    }

    {
        const int r1 = m0 + wm * 16 + (lane >> 2);
        const int r2 = r1 + 8;
        const bool ok1 = (r1 - m0) < act, ok2 = (r2 - m0) < act;
        if (ok1 || ok2) {
            const int b1i = r1 >> lvl, j1 = (nl - 1) + (r1 & (nl - 1));
            const int b2i = r2 >> lvl, j2 = (nl - 1) + (r2 & (nl - 1));
            const size_t n1 = (size_t)(b1i * 63 + j1) * 128;
            const size_t n2 = (size_t)(b2i * 63 + j2) * 128;
            #pragma unroll
            for (int j8 = 0; j8 < 4; j8++) {
                const int n = wn * 32 + j8 * 8 + (lane & 3) * 2;
                float2 bb = *(const float2*)(b2 + n);
                float v0 = fmaxf(C2[j8][0] + bb.x, 0.f), v1 = fmaxf(C2[j8][1] + bb.y, 0.f);
                float v2 = fmaxf(C2[j8][2] + bb.x, 0.f), v3 = fmaxf(C2[j8][3] + bb.y, 0.f);
                uint32_t h01, l01, h23, l23;
                split2(v0, v1, h01, l01); split2(v2, v3, h23, l23);
                if (ok1) { *(uint32_t*)(g_reph + n1 + n) = h01; *(uint32_t*)(g_repl + n1 + n) = l01; }
                if (ok2) { *(uint32_t*)(g_reph + n2 + n) = h23; *(uint32_t*)(g_repl + n2 + n) = l23; }
            }
        }
    }
}

// Tail kernel (r10 verbatim): levels 2..0 fused, 16 batches/CTA, grid 128.
__global__ void __launch_bounds__(512, 1) tree_tail_kernel(
    const float* __restrict__ b1, const float* __restrict__ b2)
{
    extern __shared__ char smem[];
    const uint32_t sb = smem_u32(smem);
    const int tid = threadIdx.x, lane = tid & 31;
    const int wid = tid >> 5;
    const int wm = wid & 3, wn = wid >> 2;
    const int bat0 = blockIdx.x * 16;

    tree_body64(smem, sb, tid, lane, wm, wn, b1, b2, 2, bat0 * 4, 64);
    __syncthreads();
    tree_body64(smem, sb, tid, lane, wm, wn, b1, b2, 1, bat0 * 2, 32);
    __syncthreads();
    tree_body64(smem, sb, tid, lane, wm, wn, b1, b2, 0, bat0, 16);
}

// ============================================================
// Fused tree level (r10 verbatim), templated on MT. l4 (128), l3 (64).
// ============================================================
template<int MT>
__global__ void __launch_bounds__(512, 1) tree_fused_kernel(
    const float* __restrict__ b1, const float* __restrict__ b2, int lvl, int nch)
{
    constexpr int TCNT = MT / 64;
    constexpr int ABUF = MT * 256;
    constexpr int WROW = MT / 4;
    extern __shared__ char smem[];
    const uint32_t sb = smem_u32(smem);
    const int tid = threadIdx.x, m0 = blockIdx.x * MT;
    const int wid = tid >> 5, lane = tid & 31;
    const int wm = wid & 3, wn = wid >> 2;
    const int nl = 1 << lvl;

    auto loadA1 = [&](int c, int buf) {
        const uint32_t base = sb + buf * ABUF;
        #pragma unroll
        for (int i = 0; i < (MT * 16) / 512; i++) {
            int idx = i * 512 + tid;
            int half = (idx >= MT * 8);
            int j = idx & (MT * 8 - 1);
            int row = j >> 3, q = j & 7;
            int lm = m0 + row, lb = lm >> lvl, lj = (nl - 1) + (lm & (nl - 1));
            const __nv_bfloat16* src;
            if (c < 4)      src = (half ? g_X1l : g_X1h) + (size_t)(lb * 63 + lj) * 256 + c * 64 + q * 8;
            else if (c < 6) src = (half ? g_repl : g_reph) + (size_t)(lb * 63 + 2 * lj + 1) * 128 + (c - 4) * 64 + q * 8;
            else            src = (half ? g_repl : g_reph) + (size_t)(lb * 63 + 2 * lj + 2) * 128 + (c - 6) * 64 + q * 8;
            cpa16(base + half * (MT * 128) + SWZ((uint32_t)(row * 128 + q * 16)), src);
        }
    };
    auto loadB1 = [&](int c, int buf) {
        const uint32_t base = sb + 65536 + buf * 65536;
        #pragma unroll
        for (int i = 0; i < 8; i++) {
            int idx = i * 512 + tid;
            int half = idx >> 11, j = idx & 2047, n = j >> 3, q = j & 7;
            cpa16(base + half * 32768 + SWZ((uint32_t)(n * 128 + q * 16)),
                  (half ? g_W1l : g_W1h) + (size_t)n * 512 + c * 64 + q * 8);
        }
    };
    auto loadB2 = [&](int c, int buf) {
        const uint32_t base = sb + buf * 32768;
        #pragma unroll
        for (int i = 0; i < 4; i++) {
            int idx = i * 512 + tid;
            int half = idx >> 10, j = idx & 1023, n = j >> 3, q = j & 7;
            cpa16(base + half * 16384 + SWZ((uint32_t)(n * 128 + q * 16)),
                  (half ? g_W2l : g_W2h) + (size_t)n * 256 + c * 64 + q * 8);
        }
    };

    float C[TCNT][8][4] = {};
    loadB1(0, 0); loadA1(0, 0); cpcommit();
    for (int c = 0; c < nch; c++) {
        const int buf = c & 1;
        if (c + 1 < nch) { loadB1(c + 1, buf ^ 1); loadA1(c + 1, buf ^ 1); cpcommit(); cpwait1(); }
        else cpwait0();
        __syncthreads();
        const uint32_t aH = sb + buf * ABUF, aL = aH + MT * 128;
        const uint32_t bH = sb + 65536 + buf * 65536, bL = bH + 32768;
        #pragma unroll
        for (int k16 = 0; k16 < 4; k16++) {
            const int k0 = k16 * 16;
            uint32_t ah[TCNT][4], al[TCNT][4];
            const uint32_t abase = (uint32_t)((wm * WROW + (lane & 15)) * 128 + k0 * 2 + (lane >> 4) * 16);
            #pragma unroll
            for (int t = 0; t < TCNT; t++) {
                uint32_t o = SWZ(abase + t * 2048);
                ldsm4(ah[t], aH + o);
                ldsm4(al[t], aL + o);
            }
            #pragma unroll
            for (int j = 0; j < 4; j++) {
                const int brow = wn * 64 + j * 16 + ((lane >> 4) << 3) + (lane & 7);
                const uint32_t bo = SWZ((uint32_t)(brow * 128 + (k0 + ((lane >> 3) & 1) * 8) * 2));
                uint32_t bh[4], bl[4];
                ldsm4(bh, bH + bo);
                ldsm4(bl, bL + bo);
                #pragma unroll
                for (int t = 0; t < TCNT; t++) { mma16816(C[t][2 * j], ah[t], bh); mma16816(C[t][2 * j + 1], ah[t], bh + 2); }
                #pragma unroll
                for (int t = 0; t < TCNT; t++) { mma16816(C[t][2 * j], al[t], bh); mma16816(C[t][2 * j + 1], al[t], bh + 2); }
                #pragma unroll
                for (int t = 0; t < TCNT; t++) { mma16816(C[t][2 * j], ah[t], bl); mma16816(C[t][2 * j + 1], ah[t], bl + 2); }
            }
        }
        __syncthreads();
    }

    loadB2(0, 0); cpcommit();
    loadB2(1, 1); cpcommit();
    #pragma unroll
    for (int t = 0; t < TCNT; t++) {
        const int rloc = wm * WROW + t * 16 + (lane >> 2);
        #pragma unroll
        for (int j8 = 0; j8 < 8; j8++) {
            const int n0 = wn * 64 + j8 * 8 + (lane & 3) * 2;
            float2 bb = *(const float2*)(b1 + n0);
            float v0 = fmaxf(C[t][j8][0] + bb.x, 0.f), v1 = fmaxf(C[t][j8][1] + bb.y, 0.f);
            float v2 = fmaxf(C[t][j8][2] + bb.x, 0.f), v3 = fmaxf(C[t][j8][3] + bb.y, 0.f);
            uint32_t h01, l01, h23, l23;
            split2(v0, v1, h01, l01); split2(v2, v3, h23, l23);
            const uint32_t cbase = 65536 + (n0 >> 6) * (MT * 128);
            const uint32_t o1 = SWZ((uint32_t)(rloc * 128 + (n0 & 63) * 2));
            const uint32_t o2 = SWZ((uint32_t)((rloc + 8) * 128 + (n0 & 63) * 2));
            *(uint32_t*)(smem + cbase + o1)         = h01;
            *(uint32_t*)(smem + cbase + 65536 + o1) = l01;
            *(uint32_t*)(smem + cbase + o2)         = h23;
            *(uint32_t*)(smem + cbase + 65536 + o2) = l23;
        }
    }
    __syncthreads();

    float C2[TCNT][4][4] = {};
    for (int c2 = 0; c2 < 4; c2++) {
        if (c2 < 3) cpwait1(); else cpwait0();
        __syncthreads();
        const uint32_t aH = sb + 65536 + c2 * (MT * 128), aL = aH + 65536;
        const uint32_t bH = sb + (c2 & 1) * 32768,        bL = bH + 16384;
        #pragma unroll
        for (int k16 = 0; k16 < 4; k16++) {
            const int k0 = k16 * 16;
            uint32_t ah[TCNT][4], al[TCNT][4];
            const uint32_t abase = (uint32_t)((wm * WROW + (lane & 15)) * 128 + k0 * 2 + (lane >> 4) * 16);
            #pragma unroll
            for (int t = 0; t < TCNT; t++) {
                uint32_t o = SWZ(abase + t * 2048);
                ldsm4(ah[t], aH + o);
                ldsm4(al[t], aL + o);
            }
            #pragma unroll
            for (int j = 0; j < 2; j++) {
                const int brow = wn * 32 + j * 16 + ((lane >> 4) << 3) + (lane & 7);
                const uint32_t bo = SWZ((uint32_t)(brow * 128 + (k0 + ((lane >> 3) & 1) * 8) * 2));
                uint32_t bh[4], bl[4];
                ldsm4(bh, bH + bo);
                ldsm4(bl, bL + bo);
                #pragma unroll
                for (int t = 0; t < TCNT; t++) { mma16816(C2[t][2 * j], ah[t], bh); mma16816(C2[t][2 * j + 1], ah[t], bh + 2); }
                #pragma unroll
                for (int t = 0; t < TCNT; t++) { mma16816(C2[t][2 * j], al[t], bh); mma16816(C2[t][2 * j + 1], al[t], bh + 2); }
                #pragma unroll
                for (int t = 0; t < TCNT; t++) { mma16816(C2[t][2 * j], ah[t], bl); mma16816(C2[t][2 * j + 1], ah[t], bl + 2); }
            }
        }
        __syncthreads();
        if (c2 + 2 < 4) loadB2(c2 + 2, c2 & 1);
        cpcommit();
    }

    #pragma unroll
    for (int t = 0; t < TCNT; t++) {
        const int r1 = m0 + wm * WROW + t * 16 + (lane >> 2);
        const int r2 = r1 + 8;
        const int b1i = r1 >> lvl, j1 = (nl - 1) + (r1 & (nl - 1));
        const int b2i = r2 >> lvl, j2 = (nl - 1) + (r2 & (nl - 1));
        const size_t n1 = (size_t)(b1i * 63 + j1) * 128;
        const size_t n2 = (size_t)(b2i * 63 + j2) * 128;
        #pragma unroll
        for (int j8 = 0; j8 < 4; j8++) {
            const int n = wn * 32 + j8 * 8 + (lane & 3) * 2;
            float2 bb = *(const float2*)(b2 + n);
            float v0 = fmaxf(C2[t][j8][0] + bb.x, 0.f), v1 = fmaxf(C2[t][j8][1] + bb.y, 0.f);
            float v2 = fmaxf(C2[t][j8][2] + bb.x, 0.f), v3 = fmaxf(C2[t][j8][3] + bb.y, 0.f);
            uint32_t h01, l01, h23, l23;
            split2(v0, v1, h01, l01); split2(v2, v3, h23, l23);
            *(uint32_t*)(g_reph + n1 + n) = h01; *(uint32_t*)(g_repl + n1 + n) = l01;
            *(uint32_t*)(g_reph + n2 + n) = h23; *(uint32_t*)(g_repl + n2 + n) = l23;
        }
    }
}

// ---- heads ----
__global__ void __launch_bounds__(128) heads_kernel(
    const float* __restrict__ Wc1, const float* __restrict__ bc1,
    const float* __restrict__ Wc2, const float* __restrict__ bc2,
    const float* __restrict__ Wc3, const float* __restrict__ bc3,
    const float* __restrict__ Wd1, const float* __restrict__ bd1,
    const float* __restrict__ Wd2, const float* __restrict__ bd2,
    const float* __restrict__ Wd3, const float* __restrict__ bd3,
    float* __restrict__ out)
{
    __shared__ float sroot[128];
    __shared__ float sh1[128];
    __shared__ float sprod[128];
    int b = blockIdx.x, t = threadIdx.x;
    size_t ro = (size_t)(b * 63) * 128 + t;
    sroot[t] = __bfloat162float(g_reph[ro]) + __bfloat162float(g_repl[ro]);
    __syncthreads();

    int head = t >> 6, c = t & 63;
    const float* W1 = head ? Wd1 : Wc1; const float* B1 = head ? bd1 : bc1;
    const float* W2 = head ? Wd2 : Wc2; const float* B2 = head ? bd2 : bc2;
    const float* W3 = head ? Wd3 : Wc3; const float* B3 = head ? bd3 : bc3;

    float h = B1[c];
    #pragma unroll 8
    for (int k = 0; k < 128; k++) h += sroot[k] * W1[k * 64 + c];
    sh1[t] = fmaxf(h, 0.f);
    __syncthreads();

    float h2 = B2[c];
    #pragma unroll 8
    for (int k = 0; k < 64; k++) h2 += sh1[head * 64 + k] * W2[k * 64 + c];
    h2 = fmaxf(h2, 0.f);
    sprod[t] = h2 * W3[c];
    __syncthreads();

    if (c == 0) {
        float s = B3[0];
        #pragma unroll 8
        for (int k = 0; k < 64; k++) s += sprod[head * 64 + k];
        out[head * BSZ + b] = 1.f / (1.f + expf(-s));
    }
}

// ---- launch ----
#define SM_TREE 196608
#define SM_L5   98304
#define SM_IN   65536

extern "C" void kernel_launch(void* const* d_in, const int* in_sizes, int n_in,
                              void* d_out, int out_size)
{
    const float* op      = (const float*)d_in[0];
    const float* extra   = (const float*)d_in[1];
    const float* cond1   = (const float*)d_in[2];
    const float* cond2   = (const float*)d_in[3];
    const float* bitmap  = (const float*)d_in[4];
    const float* hascond = (const float*)d_in[5];
    const float* W_op = (const float*)d_in[6];   const float* b_op = (const float*)d_in[7];
    const float* W_pr = (const float*)d_in[8];   const float* b_pr = (const float*)d_in[9];
    const float* W_bm = (const float*)d_in[10];  const float* b_bm = (const float*)d_in[11];
    const float* W_r1 = (const float*)d_in[12];  const float* b_r1 = (const float*)d_in[13];
    const float* W_r2 = (const float*)d_in[14];  const float* b_r2 = (const float*)d_in[15];
    const float* W_c1 = (const float*)d_in[16];  const float* b_c1 = (const float*)d_in[17];
    const float* W_c2 = (const float*)d_in[18];  const float* b_c2 = (const float*)d_in[19];
    const float* W_c3 = (const float*)d_in[20];  const float* b_c3 = (const float*)d_in[21];
    const float* W_d1 = (const float*)d_in[22];  const float* b_d1 = (const float*)d_in[23];
    const float* W_d2 = (const float*)d_in[24];  const float* b_d2 = (const float*)d_in[25];
    const float* W_d3 = (const float*)d_in[26];  const float* b_d3 = (const float*)d_in[27];

    cudaFuncSetAttribute(tree_fused_kernel<128>, cudaFuncAttributeMaxDynamicSharedMemorySize, SM_TREE);
    cudaFuncSetAttribute(tree_fused_kernel<64>,  cudaFuncAttributeMaxDynamicSharedMemorySize, SM_TREE);
    cudaFuncSetAttribute(tree_tail_kernel,       cudaFuncAttributeMaxDynamicSharedMemorySize, SM_TREE);
    cudaFuncSetAttribute(l5_kernel,              cudaFuncAttributeMaxDynamicSharedMemorySize, SM_L5);
    cudaFuncSetAttribute(input_kernel,           cudaFuncAttributeMaxDynamicSharedMemorySize, SM_IN);

    prep_kernel<<<928, 256>>>(W_r1, W_r2, W_bm, W_op, W_pr);
    input_kernel<<<NROWS / 64, 256, SM_IN>>>(op, extra, cond1, cond2, bitmap, hascond,
                                             b_op, b_pr, b_bm);

    l5_kernel<<<(BSZ << 5) / 64, 256, SM_L5>>>(b_r1, b_r2);
    tree_fused_kernel<128><<<(BSZ << 4) / 128, 512, SM_TREE>>>(b_r1, b_r2, 4, 8);
    tree_fused_kernel<64> <<<(BSZ << 3) / 64,  512, SM_TREE>>>(b_r1, b_r2, 3, 8);
    tree_tail_kernel<<<BSZ / 16, 512, SM_TREE>>>(b_r1, b_r2);

    heads_kernel<<<BSZ, 128>>>(W_c1, b_c1, W_c2, b_c2, W_c3, b_c3,
                               W_d1, b_d1, W_d2, b_d2, W_d3, b_d3,
                               (float*)d_out);
}